// round 2
// baseline (speedup 1.0000x reference)
#include <cuda_runtime.h>
#include <cuda_bf16.h>
#include <cstdint>

// Problem constants (fixed by the dataset)
#define N_TOK 2048
#define D_IN  2048
#define D_OUT 2048
#define NEXP  8
#define TOPK  2
#define NFLAT (N_TOK * TOPK)   // 4096

// GEMM tiling
#define BM 128
#define BN 128
#define BK 16
#define KT (D_IN / BK)         // 128 k-iterations
#define MAX_TILES 40           // ceil(4096/128) + (NEXP-1) padding tiles, rounded up
#define LDS 24                 // SMEM row stride in elements (16 + 8 pad; conflict-free)

// -------- device-global scratch (no allocations allowed) --------
__device__ int   g_tile_expert[MAX_TILES];
__device__ int   g_tile_start[MAX_TILES];
__device__ int   g_tile_end[MAX_TILES];
__device__ int   g_ntiles;
__device__ float g_y[(size_t)NFLAT * D_OUT];   // gated per-slot outputs, indexed by flat j

// -------- kernel 1: build per-expert M-tile descriptors on device --------
__global__ void build_tiles_kernel(const int* __restrict__ expert_offsets) {
    if (threadIdx.x != 0) return;
    int t = 0, prev = 0;
    for (int e = 0; e < NEXP; e++) {
        int end = expert_offsets[e];   // inclusive cumsum
        for (int s = prev; s < end; s += BM) {
            g_tile_expert[t] = e;
            g_tile_start[t]  = s;
            g_tile_end[t]    = (end < s + BM) ? end : (s + BM);
            t++;
        }
        prev = end;
    }
    g_ntiles = t;
    for (int i = t; i < MAX_TILES; i++) { g_tile_expert[i] = 0; g_tile_start[i] = 0; g_tile_end[i] = 0; }
}

// -------- bf16 split helpers --------
__device__ __forceinline__ void split_store(__nv_bfloat16* h, __nv_bfloat16* l,
                                            int off, float4 v) {
    __nv_bfloat16 hx = __float2bfloat16(v.x);
    __nv_bfloat16 hy = __float2bfloat16(v.y);
    __nv_bfloat16 hz = __float2bfloat16(v.z);
    __nv_bfloat16 hw = __float2bfloat16(v.w);
    *(__nv_bfloat162*)(h + off)     = __halves2bfloat162(hx, hy);
    *(__nv_bfloat162*)(h + off + 2) = __halves2bfloat162(hz, hw);
    __nv_bfloat16 lx = __float2bfloat16(v.x - __bfloat162float(hx));
    __nv_bfloat16 ly = __float2bfloat16(v.y - __bfloat162float(hy));
    __nv_bfloat16 lz = __float2bfloat16(v.z - __bfloat162float(hz));
    __nv_bfloat16 lw = __float2bfloat16(v.w - __bfloat162float(hw));
    *(__nv_bfloat162*)(l + off)     = __halves2bfloat162(lx, ly);
    *(__nv_bfloat162*)(l + off + 2) = __halves2bfloat162(lz, lw);
}

__device__ __forceinline__ void mma_bf16(float* d, const uint32_t* a, const uint32_t* b) {
    asm volatile(
        "mma.sync.aligned.m16n8k16.row.col.f32.bf16.bf16.f32 "
        "{%0,%1,%2,%3}, {%4,%5,%6,%7}, {%8,%9}, {%0,%1,%2,%3};"
        : "+f"(d[0]), "+f"(d[1]), "+f"(d[2]), "+f"(d[3])
        : "r"(a[0]), "r"(a[1]), "r"(a[2]), "r"(a[3]), "r"(b[0]), "r"(b[1]));
}

// -------- kernel 2: grouped GEMM with gather + gated scatter epilogue --------
__global__ __launch_bounds__(256, 1) void moe_gemm_kernel(
    const float* __restrict__ inputs,     // [N_TOK, D_IN]
    const float* __restrict__ weight,     // [NEXP, D_OUT, D_IN]
    const int*   __restrict__ ssi,        // sorted_scattered_idxs [NFLAT]
    const float* __restrict__ gates)      // [N_TOK, TOPK] flat
{
    const int tile = blockIdx.x;
    if (tile >= g_ntiles) return;
    const int e         = g_tile_expert[tile];
    const int row_start = g_tile_start[tile];
    const int row_end   = g_tile_end[tile];
    const int n0        = blockIdx.y * BN;

    // 4 * 2 * 128 * 24 * 2B = 49152 bytes (exactly the 48KB static limit)
    __shared__ __nv_bfloat16 sAh[2][BM * LDS];
    __shared__ __nv_bfloat16 sAl[2][BM * LDS];
    __shared__ __nv_bfloat16 sBh[2][BN * LDS];
    __shared__ __nv_bfloat16 sBl[2][BN * LDS];

    const int tid  = threadIdx.x;
    const int warp = tid >> 5;
    const int lane = tid & 31;
    const int wm   = warp >> 2;        // 0..1  -> rows wm*64
    const int wn   = warp & 3;         // 0..3  -> cols wn*32
    const int g    = lane >> 2;        // 0..7
    const int tg   = lane & 3;         // 0..3

    // ---- loader mapping: each thread owns 2 rows x one float4 column ----
    const int rA0  = tid >> 2;         // 0..63
    const int rA1  = rA0 + 64;
    const int colf = (tid & 3) * 4;    // float column within BK
    const int pA0 = row_start + rA0;
    const int pA1 = row_start + rA1;
    const int tok0 = (pA0 < row_end) ? (ssi[pA0] >> 1) : 0;
    const int tok1 = (pA1 < row_end) ? (ssi[pA1] >> 1) : 0;
    const float* gA0 = inputs + (size_t)tok0 * D_IN + colf;
    const float* gA1 = inputs + (size_t)tok1 * D_IN + colf;
    const float* wb  = weight + (size_t)e * D_OUT * D_IN;
    const float* gB0 = wb + (size_t)(n0 + rA0) * D_IN + colf;
    const float* gB1 = wb + (size_t)(n0 + rA1) * D_IN + colf;
    const int offA0 = rA0 * LDS + colf;
    const int offA1 = rA1 * LDS + colf;

    float C[4][4][4];
#pragma unroll
    for (int i = 0; i < 4; i++)
#pragma unroll
        for (int j = 0; j < 4; j++)
#pragma unroll
            for (int r = 0; r < 4; r++) C[i][j][r] = 0.0f;

    // ---- prologue: stage 0 ----
    float4 fa0 = *(const float4*)(gA0);
    float4 fa1 = *(const float4*)(gA1);
    float4 fb0 = *(const float4*)(gB0);
    float4 fb1 = *(const float4*)(gB1);
    split_store(sAh[0], sAl[0], offA0, fa0);
    split_store(sAh[0], sAl[0], offA1, fa1);
    split_store(sBh[0], sBl[0], offA0, fb0);
    split_store(sBh[0], sBl[0], offA1, fb1);

    for (int kt = 0; kt < KT; kt++) {
        __syncthreads();
        const int buf = kt & 1;
        const bool more = (kt + 1) < KT;
        if (more) {
            const int ko = (kt + 1) * BK;
            fa0 = *(const float4*)(gA0 + ko);
            fa1 = *(const float4*)(gA1 + ko);
            fb0 = *(const float4*)(gB0 + ko);
            fb1 = *(const float4*)(gB1 + ko);
        }

        // ---- fragment loads ----
        uint32_t ah[4][4], al[4][4], bh[4][2], bl[4][2];
        const __nv_bfloat16* Ah = sAh[buf];
        const __nv_bfloat16* Al = sAl[buf];
        const __nv_bfloat16* Bh = sBh[buf];
        const __nv_bfloat16* Bl = sBl[buf];
        const int abase = (wm * 64 + g) * LDS + 2 * tg;
#pragma unroll
        for (int mt = 0; mt < 4; mt++) {
            const int o = abase + mt * 16 * LDS;
            ah[mt][0] = *(const uint32_t*)(Ah + o);
            ah[mt][1] = *(const uint32_t*)(Ah + o + 8 * LDS);
            ah[mt][2] = *(const uint32_t*)(Ah + o + 8);
            ah[mt][3] = *(const uint32_t*)(Ah + o + 8 * LDS + 8);
            al[mt][0] = *(const uint32_t*)(Al + o);
            al[mt][1] = *(const uint32_t*)(Al + o + 8 * LDS);
            al[mt][2] = *(const uint32_t*)(Al + o + 8);
            al[mt][3] = *(const uint32_t*)(Al + o + 8 * LDS + 8);
        }
        const int bbase = (wn * 32 + g) * LDS + 2 * tg;
#pragma unroll
        for (int nt = 0; nt < 4; nt++) {
            const int o = bbase + nt * 8 * LDS;
            bh[nt][0] = *(const uint32_t*)(Bh + o);
            bh[nt][1] = *(const uint32_t*)(Bh + o + 8);
            bl[nt][0] = *(const uint32_t*)(Bl + o);
            bl[nt][1] = *(const uint32_t*)(Bl + o + 8);
        }

        // ---- 3-way split MMA: hi*hi + hi*lo + lo*hi ----
#pragma unroll
        for (int mt = 0; mt < 4; mt++)
#pragma unroll
            for (int nt = 0; nt < 4; nt++) {
                mma_bf16(C[mt][nt], ah[mt], bh[nt]);
                mma_bf16(C[mt][nt], ah[mt], bl[nt]);
                mma_bf16(C[mt][nt], al[mt], bh[nt]);
            }

        if (more) {
            const int nb = (kt + 1) & 1;
            split_store(sAh[nb], sAl[nb], offA0, fa0);
            split_store(sAh[nb], sAl[nb], offA1, fa1);
            split_store(sBh[nb], sBl[nb], offA0, fb0);
            split_store(sBh[nb], sBl[nb], offA1, fb1);
        }
    }

    // ---- epilogue: gate + scatter rows to g_y[flat_j] ----
#pragma unroll
    for (int mt = 0; mt < 4; mt++) {
        const int r0 = wm * 64 + mt * 16 + g;
        const int r1 = r0 + 8;
        const int p0 = row_start + r0;
        const int p1 = row_start + r1;
        int   j0 = 0, j1 = 0;
        float g0 = 0.f, g1 = 0.f;
        const bool v0 = p0 < row_end;
        const bool v1 = p1 < row_end;
        if (v0) { j0 = ssi[p0]; g0 = gates[j0]; }
        if (v1) { j1 = ssi[p1]; g1 = gates[j1]; }
#pragma unroll
        for (int nt = 0; nt < 4; nt++) {
            const int col = n0 + wn * 32 + nt * 8 + 2 * tg;
            if (v0) {
                float2 o = make_float2(C[mt][nt][0] * g0, C[mt][nt][1] * g0);
                *(float2*)(g_y + (size_t)j0 * D_OUT + col) = o;
            }
            if (v1) {
                float2 o = make_float2(C[mt][nt][2] * g1, C[mt][nt][3] * g1);
                *(float2*)(g_y + (size_t)j1 * D_OUT + col) = o;
            }
        }
    }
}

// -------- kernel 3: combine the TOPK=2 gated slot outputs per token --------
__global__ void combine_kernel(float* __restrict__ out) {
    const int i = blockIdx.x * blockDim.x + threadIdx.x;  // over N_TOK*D_OUT/4
    if (i >= N_TOK * D_OUT / 4) return;
    const int n = i >> 9;          // D_OUT/4 = 512 float4 per row
    const int c = i & 511;
    const float4* y = (const float4*)g_y;
    float4 a = y[(size_t)(2 * n) * 512 + c];
    float4 b = y[(size_t)(2 * n + 1) * 512 + c];
    float4 o;
    o.x = a.x + b.x; o.y = a.y + b.y; o.z = a.z + b.z; o.w = a.w + b.w;
    ((float4*)out)[i] = o;
}

extern "C" void kernel_launch(void* const* d_in, const int* in_sizes, int n_in,
                              void* d_out, int out_size) {
    const float* inputs         = (const float*)d_in[0];
    const float* weight         = (const float*)d_in[1];
    // d_in[2] = k (TOPK) scalar, hardcoded
    // d_in[3] = sorted_expert_idxs (unused; tiles derived from offsets)
    const int*   ssi            = (const int*)d_in[4];
    // d_in[5] = padded_block_idxs (unused)
    const int*   expert_offsets = (const int*)d_in[6];
    const float* gates          = (const float*)d_in[7];
    float*       out            = (float*)d_out;

    build_tiles_kernel<<<1, 32>>>(expert_offsets);

    dim3 grid(MAX_TILES, D_OUT / BN);
    moe_gemm_kernel<<<grid, 256>>>(inputs, weight, ssi, gates);

    combine_kernel<<<(N_TOK * D_OUT / 4 + 255) / 256, 256>>>(out);
}

// round 5
// speedup vs baseline: 1.3860x; 1.3860x over previous
#include <cuda_runtime.h>
#include <cuda_bf16.h>
#include <cstdint>

// ---------------- problem constants ----------------
#define N_TOK 2048
#define D_IN  2048
#define D_OUT 2048
#define NEXP  8
#define NFLAT 4096

// ---------------- tiling ----------------
#define BM 128
#define BN 128
#define BK 16
#define KT (D_IN / BK)     // 128
#define MAX_TILES 40
#define LDS 24             // smem row stride (elements); conflict-free for ldmatrix

__device__ __forceinline__ uint32_t smem_u32(const void* p) {
    uint32_t a;
    asm("{ .reg .u64 t; cvta.to.shared.u64 t, %1; cvt.u32.u64 %0, t; }" : "=r"(a) : "l"(p));
    return a;
}

__device__ __forceinline__ void mma_bf16(float* d, const uint32_t* a, const uint32_t* b) {
    asm volatile(
        "mma.sync.aligned.m16n8k16.row.col.f32.bf16.bf16.f32 "
        "{%0,%1,%2,%3}, {%4,%5,%6,%7}, {%8,%9}, {%0,%1,%2,%3};"
        : "+f"(d[0]), "+f"(d[1]), "+f"(d[2]), "+f"(d[3])
        : "r"(a[0]), "r"(a[1]), "r"(a[2]), "r"(a[3]), "r"(b[0]), "r"(b[1]));
}

#define LDMATRIX_X4(r0, r1, r2, r3, addr)                                  \
    asm volatile("ldmatrix.sync.aligned.m8n8.x4.shared.b16 {%0,%1,%2,%3}, [%4];" \
        : "=r"(r0), "=r"(r1), "=r"(r2), "=r"(r3) : "r"(addr))

// split a float4 into bf16 hi/lo and store 8B to each region
__device__ __forceinline__ void split_store(__nv_bfloat16* h, __nv_bfloat16* l,
                                            int off, float4 v) {
    __nv_bfloat162 h01 = __float22bfloat162_rn(make_float2(v.x, v.y));
    __nv_bfloat162 h23 = __float22bfloat162_rn(make_float2(v.z, v.w));
    *(__nv_bfloat162*)(h + off)     = h01;
    *(__nv_bfloat162*)(h + off + 2) = h23;
    float2 hf01 = __bfloat1622float2(h01);
    float2 hf23 = __bfloat1622float2(h23);
    __nv_bfloat162 l01 = __float22bfloat162_rn(make_float2(v.x - hf01.x, v.y - hf01.y));
    __nv_bfloat162 l23 = __float22bfloat162_rn(make_float2(v.z - hf23.x, v.w - hf23.y));
    *(__nv_bfloat162*)(l + off)     = l01;
    *(__nv_bfloat162*)(l + off + 2) = l23;
}

// ---------------- kernel 1: zero output ----------------
__global__ void zero_out_kernel(float4* __restrict__ out) {
    out[blockIdx.x * 256 + threadIdx.x] = make_float4(0.f, 0.f, 0.f, 0.f);
}

// ---------------- kernel 2: grouped GEMM ----------------
__global__ __launch_bounds__(256, 2) void moe_gemm_kernel(
    const float* __restrict__ inputs,     // [N_TOK, D_IN]
    const float* __restrict__ weight,     // [NEXP, D_OUT, D_IN]
    const int*   __restrict__ ssi,        // [NFLAT]
    const float* __restrict__ gates,      // [N_TOK*TOPK] flat
    const int*   __restrict__ expert_offsets,
    float*       __restrict__ out)        // [N_TOK, D_OUT] (pre-zeroed)
{
    // ---- derive (expert, row range) for this tile id (all threads, ~8 iters) ----
    const int tile = blockIdx.x;
    int e = -1, row_start = 0, row_end = 0;
    {
        int acc = 0, prev = 0;
        #pragma unroll
        for (int ee = 0; ee < NEXP; ee++) {
            int end = expert_offsets[ee];
            int nt = (end - prev + BM - 1) / BM;
            if (e < 0 && tile < acc + nt) {
                e = ee;
                row_start = prev + (tile - acc) * BM;
                row_end = end;
            }
            acc += nt; prev = end;
        }
        if (e < 0) return;                 // beyond last tile
        if (row_start + BM < row_end) row_end = row_start + BM;
    }
    const int n0 = blockIdx.y * BN;

    // 4 regions x 2 bufs x 128 x 24 x 2B = 49152 B (fits 2 CTAs/SM)
    __shared__ __nv_bfloat16 sAh[2][BM * LDS];
    __shared__ __nv_bfloat16 sAl[2][BM * LDS];
    __shared__ __nv_bfloat16 sBh[2][BN * LDS];
    __shared__ __nv_bfloat16 sBl[2][BN * LDS];

    const int tid  = threadIdx.x;
    const int warp = tid >> 5;
    const int lane = tid & 31;
    const int wm   = warp >> 2;        // 0..1 -> rows wm*64
    const int wn   = warp & 3;         // 0..3 -> cols wn*32
    const int g    = lane >> 3;        // ldmatrix lane group 0..3
    const int gg   = lane >> 2;        // mma row group 0..7
    const int tg   = lane & 3;

    // ---- producer mapping: 2 rows x one float4 column per thread ----
    const int rA0  = tid >> 2;         // 0..63
    const int rA1  = rA0 + 64;
    const int colf = (tid & 3) * 4;
    const int pA0 = row_start + rA0;
    const int pA1 = row_start + rA1;
    const int tok0 = (pA0 < row_end) ? (ssi[pA0] >> 1) : 0;
    const int tok1 = (pA1 < row_end) ? (ssi[pA1] >> 1) : 0;
    const float* gA0 = inputs + (size_t)tok0 * D_IN + colf;
    const float* gA1 = inputs + (size_t)tok1 * D_IN + colf;
    const float* wb  = weight + (size_t)e * D_OUT * D_IN;
    const float* gB0 = wb + (size_t)(n0 + rA0) * D_IN + colf;
    const float* gB1 = wb + (size_t)(n0 + rA1) * D_IN + colf;
    const int offA0 = rA0 * LDS + colf;
    const int offA1 = rA1 * LDS + colf;

    // ---- ldmatrix per-lane byte offsets (within a region) ----
    // A x4: rows base+ (lane&15), k-half = lane>>4
    const uint32_t aOff = (uint32_t)(((wm * 64 + (lane & 15)) * LDS + (lane >> 4) * 8) * 2);
    // B x4 (two nt per ldmatrix): row = wn*32 + (lane&7) + ((g>>1)*8), k-half = g&1
    const uint32_t bOff = (uint32_t)(((wn * 32 + (lane & 7) + ((g >> 1) * 8)) * LDS + (g & 1) * 8) * 2);

    const uint32_t baseAh = smem_u32(sAh), baseAl = smem_u32(sAl);
    const uint32_t baseBh = smem_u32(sBh), baseBl = smem_u32(sBl);
    const uint32_t bufA = BM * LDS * 2;   // bytes per buffer
    const uint32_t bufB = BN * LDS * 2;

    float C[4][4][4];
#pragma unroll
    for (int i = 0; i < 4; i++)
#pragma unroll
        for (int j = 0; j < 4; j++)
#pragma unroll
            for (int r = 0; r < 4; r++) C[i][j][r] = 0.0f;

    // ---- prologue: fill stage 0 ----
    {
        float4 fa0 = *(const float4*)(gA0);
        float4 fa1 = *(const float4*)(gA1);
        float4 fb0 = *(const float4*)(gB0);
        float4 fb1 = *(const float4*)(gB1);
        split_store(sAh[0], sAl[0], offA0, fa0);
        split_store(sAh[0], sAl[0], offA1, fa1);
        split_store(sBh[0], sBl[0], offA0, fb0);
        split_store(sBh[0], sBl[0], offA1, fb1);
    }

    for (int kt = 0; kt < KT; kt++) {
        __syncthreads();
        const int buf = kt & 1;
        const bool more = (kt + 1) < KT;
        float4 fa0, fa1, fb0, fb1;
        if (more) {
            const int ko = (kt + 1) * BK;
            fa0 = *(const float4*)(gA0 + ko);
            fa1 = *(const float4*)(gA1 + ko);
            fb0 = *(const float4*)(gB0 + ko);
            fb1 = *(const float4*)(gB1 + ko);
        }

        // ---- B fragments: 4 ldmatrix.x4 ----
        uint32_t bh[4][2], bl[4][2];
        {
            const uint32_t bB = baseBh + buf * bufB + bOff;
            const uint32_t bL = baseBl + buf * bufB + bOff;
            LDMATRIX_X4(bh[0][0], bh[0][1], bh[1][0], bh[1][1], bB);
            LDMATRIX_X4(bh[2][0], bh[2][1], bh[3][0], bh[3][1], bB + 16 * LDS * 2);
            LDMATRIX_X4(bl[0][0], bl[0][1], bl[1][0], bl[1][1], bL);
            LDMATRIX_X4(bl[2][0], bl[2][1], bl[3][0], bl[3][1], bL + 16 * LDS * 2);
        }

        // ---- per-mt A fragments + MMA ----
#pragma unroll
        for (int mt = 0; mt < 4; mt++) {
            uint32_t ah[4], al[4];
            const uint32_t aA = baseAh + buf * bufA + aOff + mt * 16 * LDS * 2;
            const uint32_t aL = baseAl + buf * bufA + aOff + mt * 16 * LDS * 2;
            LDMATRIX_X4(ah[0], ah[1], ah[2], ah[3], aA);
            LDMATRIX_X4(al[0], al[1], al[2], al[3], aL);
#pragma unroll
            for (int nt = 0; nt < 4; nt++) {
                mma_bf16(C[mt][nt], ah, bh[nt]);
                mma_bf16(C[mt][nt], ah, bl[nt]);
                mma_bf16(C[mt][nt], al, bh[nt]);
            }
        }

        if (more) {
            const int nb = (kt + 1) & 1;
            split_store(sAh[nb], sAl[nb], offA0, fa0);
            split_store(sAh[nb], sAl[nb], offA1, fa1);
            split_store(sBh[nb], sBl[nb], offA0, fb0);
            split_store(sBh[nb], sBl[nb], offA1, fb1);
        }
    }

    // ---- epilogue: gate + atomic-add into out ----
#pragma unroll
    for (int mt = 0; mt < 4; mt++) {
        const int r0 = wm * 64 + mt * 16 + gg;
        const int r1 = r0 + 8;
        const int p0 = row_start + r0;
        const int p1 = row_start + r1;
        const bool v0 = p0 < row_end;
        const bool v1 = p1 < row_end;
        int   j0 = 0, j1 = 0;
        float g0 = 0.f, g1 = 0.f;
        if (v0) { j0 = ssi[p0]; g0 = gates[j0]; }
        if (v1) { j1 = ssi[p1]; g1 = gates[j1]; }
        float* o0 = out + (size_t)(j0 >> 1) * D_OUT + n0 + wn * 32;
        float* o1 = out + (size_t)(j1 >> 1) * D_OUT + n0 + wn * 32;
#pragma unroll
        for (int nt = 0; nt < 4; nt++) {
            const int col = nt * 8 + 2 * tg;
            if (v0) {
                atomicAdd(o0 + col,     C[mt][nt][0] * g0);
                atomicAdd(o0 + col + 1, C[mt][nt][1] * g0);
            }
            if (v1) {
                atomicAdd(o1 + col,     C[mt][nt][2] * g1);
                atomicAdd(o1 + col + 1, C[mt][nt][3] * g1);
            }
        }
    }
}

extern "C" void kernel_launch(void* const* d_in, const int* in_sizes, int n_in,
                              void* d_out, int out_size) {
    const float* inputs         = (const float*)d_in[0];
    const float* weight         = (const float*)d_in[1];
    const int*   ssi            = (const int*)d_in[4];
    const int*   expert_offsets = (const int*)d_in[6];
    const float* gates          = (const float*)d_in[7];
    float*       out            = (float*)d_out;

    zero_out_kernel<<<(N_TOK * D_OUT / 4) / 256, 256>>>((float4*)out);

    dim3 grid(MAX_TILES, D_OUT / BN);
    moe_gemm_kernel<<<grid, 256>>>(inputs, weight, ssi, gates, expert_offsets, out);
}